// round 9
// baseline (speedup 1.0000x reference)
#include <cuda_runtime.h>

#define N_NODES 50000
#define N_EDGES 800000
#define HIDDEN 64
#define OUT_DIM 16
#define NBLK 592          // 4 blocks/SM x 148 SMs
#define TPB 256
#define GSTRIDE (NBLK * TPB)
#define CHUNK 85          // ceil(50000/592)
#define TILE_N 64
#define NTILES 782        // ceil(50000/64)
#define SROW 132          // padded feature row: 128 data + 4 pad

// ---------------- device scratch ----------------
__device__ int g_count[N_NODES];
__device__ int g_off[N_NODES + 1];
__device__ int g_csr[N_EDGES];
__device__ int g_blocksum[NBLK];
__device__ int g_blockoff[NBLK];
__device__ unsigned g_bar_cnt;
__device__ unsigned g_bar_gen;
__device__ __align__(16) float g_h0[N_NODES * HIDDEN];
__device__ __align__(16) float g_h1[N_NODES * HIDDEN];

// ---------------- software grid barrier ----------------
__device__ __forceinline__ void grid_barrier() {
    __syncthreads();
    if (threadIdx.x == 0) {
        unsigned gen = *((volatile unsigned*)&g_bar_gen);
        __threadfence();
        unsigned a = atomicAdd(&g_bar_cnt, 1u);
        if (a == NBLK - 1) {
            g_bar_cnt = 0;
            __threadfence();
            atomicExch(&g_bar_gen, gen + 1u);
        } else {
            while (*((volatile unsigned*)&g_bar_gen) == gen) { __nanosleep(32); }
        }
        __threadfence();
    }
    __syncthreads();
}

__device__ __forceinline__ float4 fma4(float s, float4 w, float4 acc) {
    acc.x = fmaf(s, w.x, acc.x);
    acc.y = fmaf(s, w.y, acc.y);
    acc.z = fmaf(s, w.z, acc.z);
    acc.w = fmaf(s, w.w, acc.w);
    return acc;
}
__device__ __forceinline__ float4 relu4(float4 v) {
    v.x = fmaxf(v.x, 0.f); v.y = fmaxf(v.y, 0.f);
    v.z = fmaxf(v.z, 0.f); v.w = fmaxf(v.w, 0.f);
    return v;
}
__device__ __forceinline__ void acc4(float4& a, float4 v) {
    a.x += v.x; a.y += v.y; a.z += v.z; a.w += v.w;
}

// ---------------- gather-mean: 8 edges in flight, rows streamed L2-only ----------------
__device__ __forceinline__ float4 gather_mean(const float4* __restrict__ x4,
                                              int node, int q) {
    int s = __ldg(&g_off[node]);
    int e = __ldg(&g_off[node + 1]);
    float4 acc = make_float4(0.f, 0.f, 0.f, 0.f);
    int i = s;
    int j0 = 0, j1 = 0, j2 = 0, j3 = 0, j4 = 0, j5 = 0, j6 = 0, j7 = 0;
    if (i + 8 <= e) {
        j0 = __ldg(&g_csr[i]);     j1 = __ldg(&g_csr[i + 1]);
        j2 = __ldg(&g_csr[i + 2]); j3 = __ldg(&g_csr[i + 3]);
        j4 = __ldg(&g_csr[i + 4]); j5 = __ldg(&g_csr[i + 5]);
        j6 = __ldg(&g_csr[i + 6]); j7 = __ldg(&g_csr[i + 7]);
    }
    while (i + 8 <= e) {
        float4 v0 = __ldcg(&x4[j0 * 16 + q]);
        float4 v1 = __ldcg(&x4[j1 * 16 + q]);
        float4 v2 = __ldcg(&x4[j2 * 16 + q]);
        float4 v3 = __ldcg(&x4[j3 * 16 + q]);
        float4 v4 = __ldcg(&x4[j4 * 16 + q]);
        float4 v5 = __ldcg(&x4[j5 * 16 + q]);
        float4 v6 = __ldcg(&x4[j6 * 16 + q]);
        float4 v7 = __ldcg(&x4[j7 * 16 + q]);
        i += 8;
        if (i + 8 <= e) {  // prefetch next batch's indices while rows are in flight
            j0 = __ldg(&g_csr[i]);     j1 = __ldg(&g_csr[i + 1]);
            j2 = __ldg(&g_csr[i + 2]); j3 = __ldg(&g_csr[i + 3]);
            j4 = __ldg(&g_csr[i + 4]); j5 = __ldg(&g_csr[i + 5]);
            j6 = __ldg(&g_csr[i + 6]); j7 = __ldg(&g_csr[i + 7]);
        }
        acc4(acc, v0); acc4(acc, v1); acc4(acc, v2); acc4(acc, v3);
        acc4(acc, v4); acc4(acc, v5); acc4(acc, v6); acc4(acc, v7);
    }
    if (i + 4 <= e) {
        int a0 = __ldg(&g_csr[i]);     int a1 = __ldg(&g_csr[i + 1]);
        int a2 = __ldg(&g_csr[i + 2]); int a3 = __ldg(&g_csr[i + 3]);
        float4 v0 = __ldcg(&x4[a0 * 16 + q]);
        float4 v1 = __ldcg(&x4[a1 * 16 + q]);
        float4 v2 = __ldcg(&x4[a2 * 16 + q]);
        float4 v3 = __ldcg(&x4[a3 * 16 + q]);
        acc4(acc, v0); acc4(acc, v1); acc4(acc, v2); acc4(acc, v3);
        i += 4;
    }
    for (; i < e; i++) {
        int s0 = __ldg(&g_csr[i]);
        float4 v = __ldcg(&x4[s0 * 16 + q]);
        acc4(acc, v);
    }
    int deg = e - s;
    float invd = 1.0f / (float)(deg > 0 ? deg : 1);
    acc.x *= invd; acc.y *= invd; acc.z *= invd; acc.w *= invd;
    return acc;
}

// ---------------- one 64-node tile ----------------
template <bool FINAL>
__device__ __forceinline__ void layer_tile(
    const float* __restrict__ xin,
    const float* __restrict__ Wlg,   // [64][64]
    const float* __restrict__ Wrg,   // [64][64]
    const float* __restrict__ Wog,   // [64][16] (FINAL)
    const float* __restrict__ bl,
    const float* __restrict__ bout,
    float* __restrict__ dst,
    int tile, int tid, float* sFeat) {
    int node0 = tile * TILE_N;
    // gather: sFeat[n][0:64]=agg, [64:128]=x
    {
        int ln = tid >> 4, q = tid & 15;
        const float4* x4 = (const float4*)xin;
#pragma unroll
        for (int sub = 0; sub < 4; sub++) {
            int n = sub * 16 + ln;
            int node = node0 + n;
            float4 agg = make_float4(0.f, 0.f, 0.f, 0.f);
            float4 xv = agg;
            if (node < N_NODES) {
                agg = gather_mean(x4, node, q);
                xv = __ldcg(&x4[node * 16 + q]);
            }
            *(float4*)&sFeat[n * SROW + q * 4] = agg;
            *(float4*)&sFeat[n * SROW + 64 + q * 4] = xv;
        }
    }
    __syncthreads();

    // GEMM: 4 nodes x 4 features per thread
    int f0 = (tid & 15) * 4;
    int ngrp = tid >> 4;
    const float* r0 = &sFeat[(ngrp * 4 + 0) * SROW];
    const float* r1 = r0 + SROW;
    const float* r2 = r0 + 2 * SROW;
    const float* r3 = r0 + 3 * SROW;

    float4 bias;
    bias.x = __ldg(&bl[f0]); bias.y = __ldg(&bl[f0 + 1]);
    bias.z = __ldg(&bl[f0 + 2]); bias.w = __ldg(&bl[f0 + 3]);
    float4 acc0 = bias, acc1 = bias, acc2 = bias, acc3 = bias;

    // half 1: agg @ Wl
#pragma unroll 4
    for (int k4 = 0; k4 < 16; k4++) {
        float4 a0 = *(const float4*)&r0[k4 * 4];
        float4 a1 = *(const float4*)&r1[k4 * 4];
        float4 a2 = *(const float4*)&r2[k4 * 4];
        float4 a3 = *(const float4*)&r3[k4 * 4];
        const float* wb = &Wlg[k4 * 256 + f0];
        float4 w0 = __ldg((const float4*)&wb[0]);
        float4 w1 = __ldg((const float4*)&wb[64]);
        float4 w2 = __ldg((const float4*)&wb[128]);
        float4 w3 = __ldg((const float4*)&wb[192]);
        acc0 = fma4(a0.x, w0, acc0); acc0 = fma4(a0.y, w1, acc0);
        acc0 = fma4(a0.z, w2, acc0); acc0 = fma4(a0.w, w3, acc0);
        acc1 = fma4(a1.x, w0, acc1); acc1 = fma4(a1.y, w1, acc1);
        acc1 = fma4(a1.z, w2, acc1); acc1 = fma4(a1.w, w3, acc1);
        acc2 = fma4(a2.x, w0, acc2); acc2 = fma4(a2.y, w1, acc2);
        acc2 = fma4(a2.z, w2, acc2); acc2 = fma4(a2.w, w3, acc2);
        acc3 = fma4(a3.x, w0, acc3); acc3 = fma4(a3.y, w1, acc3);
        acc3 = fma4(a3.z, w2, acc3); acc3 = fma4(a3.w, w3, acc3);
    }
    // half 2: x @ Wr
#pragma unroll 4
    for (int k4 = 0; k4 < 16; k4++) {
        float4 a0 = *(const float4*)&r0[64 + k4 * 4];
        float4 a1 = *(const float4*)&r1[64 + k4 * 4];
        float4 a2 = *(const float4*)&r2[64 + k4 * 4];
        float4 a3 = *(const float4*)&r3[64 + k4 * 4];
        const float* wb = &Wrg[k4 * 256 + f0];
        float4 w0 = __ldg((const float4*)&wb[0]);
        float4 w1 = __ldg((const float4*)&wb[64]);
        float4 w2 = __ldg((const float4*)&wb[128]);
        float4 w3 = __ldg((const float4*)&wb[192]);
        acc0 = fma4(a0.x, w0, acc0); acc0 = fma4(a0.y, w1, acc0);
        acc0 = fma4(a0.z, w2, acc0); acc0 = fma4(a0.w, w3, acc0);
        acc1 = fma4(a1.x, w0, acc1); acc1 = fma4(a1.y, w1, acc1);
        acc1 = fma4(a1.z, w2, acc1); acc1 = fma4(a1.w, w3, acc1);
        acc2 = fma4(a2.x, w0, acc2); acc2 = fma4(a2.y, w1, acc2);
        acc2 = fma4(a2.z, w2, acc2); acc2 = fma4(a2.w, w3, acc2);
        acc3 = fma4(a3.x, w0, acc3); acc3 = fma4(a3.y, w1, acc3);
        acc3 = fma4(a3.z, w2, acc3); acc3 = fma4(a3.w, w3, acc3);
    }
    acc0 = relu4(acc0); acc1 = relu4(acc1); acc2 = relu4(acc2); acc3 = relu4(acc3);

    int nb = ngrp * 4;
    if (!FINAL) {
        int gn = node0 + nb;
        if (gn + 0 < N_NODES) *(float4*)&dst[(gn + 0) * 64 + f0] = acc0;
        if (gn + 1 < N_NODES) *(float4*)&dst[(gn + 1) * 64 + f0] = acc1;
        if (gn + 2 < N_NODES) *(float4*)&dst[(gn + 2) * 64 + f0] = acc2;
        if (gn + 3 < N_NODES) *(float4*)&dst[(gn + 3) * 64 + f0] = acc3;
        __syncthreads();
    } else {
        __syncthreads();
        *(float4*)&sFeat[(nb + 0) * SROW + f0] = acc0;
        *(float4*)&sFeat[(nb + 1) * SROW + f0] = acc1;
        *(float4*)&sFeat[(nb + 2) * SROW + f0] = acc2;
        *(float4*)&sFeat[(nb + 3) * SROW + f0] = acc3;
        __syncthreads();
        int n = tid >> 2;
        int o0 = (tid & 3) * 4;
        float4 oacc;
        oacc.x = __ldg(&bout[o0]); oacc.y = __ldg(&bout[o0 + 1]);
        oacc.z = __ldg(&bout[o0 + 2]); oacc.w = __ldg(&bout[o0 + 3]);
        const float* yr = &sFeat[n * SROW];
#pragma unroll 4
        for (int k4 = 0; k4 < 16; k4++) {
            float4 yv = *(const float4*)&yr[k4 * 4];
            const float* wb = &Wog[k4 * 64 + o0];
            float4 w0 = __ldg((const float4*)&wb[0]);
            float4 w1 = __ldg((const float4*)&wb[16]);
            float4 w2 = __ldg((const float4*)&wb[32]);
            float4 w3 = __ldg((const float4*)&wb[48]);
            oacc = fma4(yv.x, w0, oacc); oacc = fma4(yv.y, w1, oacc);
            oacc = fma4(yv.z, w2, oacc); oacc = fma4(yv.w, w3, oacc);
        }
        int gn = node0 + n;
        if (gn < N_NODES) *(float4*)&dst[gn * OUT_DIM + o0] = oacc;
        __syncthreads();
    }
}

// ---------------- persistent kernel ----------------
__global__ void __launch_bounds__(TPB, 4) fused_kernel(
    const float* __restrict__ x, const int* __restrict__ ei,
    const float* __restrict__ Wl, const float* __restrict__ bl,
    const float* __restrict__ Wr, const float* __restrict__ Wout,
    const float* __restrict__ bout, float* __restrict__ out) {
    __shared__ float sFeat[TILE_N * SROW];   // 33.8 KB
    __shared__ int sInts[8];

    int tid = threadIdx.x;
    int b = blockIdx.x;
    int gtid = b * TPB + tid;
    int lane = tid & 31, w = tid >> 5;

    // phase 0: zero counts
    for (int i = gtid; i < N_NODES; i += GSTRIDE) g_count[i] = 0;
    grid_barrier();

    // phase 1: histogram
    {
        const int4* dst4 = (const int4*)(ei + N_EDGES);
        for (int t = gtid; t < N_EDGES / 4; t += GSTRIDE) {
            int4 d = __ldg(&dst4[t]);
            atomicAdd(&g_count[d.x], 1);
            atomicAdd(&g_count[d.y], 1);
            atomicAdd(&g_count[d.z], 1);
            atomicAdd(&g_count[d.w], 1);
        }
    }
    grid_barrier();

    // phase 2a: block-local exclusive scan of CHUNK counts
    {
        int base = b * CHUNK;
        int idx = base + tid;
        int v = (tid < CHUNK && idx < N_NODES) ? g_count[idx] : 0;
        int s = v;
#pragma unroll
        for (int d = 1; d < 32; d <<= 1) {
            int tv = __shfl_up_sync(0xffffffffu, s, d);
            if (lane >= d) s += tv;
        }
        if (lane == 31) sInts[w] = s;
        __syncthreads();
        if (tid == 0) {
            int acc = 0;
#pragma unroll
            for (int k = 0; k < 8; k++) { int t2 = sInts[k]; sInts[k] = acc; acc += t2; }
        }
        __syncthreads();
        int incl = s + sInts[w];
        if (tid < CHUNK && idx < N_NODES) g_off[idx] = incl - v;
        if (tid == TPB - 1) g_blocksum[b] = incl;
    }
    grid_barrier();

    // phase 2b: block 0 scans the NBLK block sums (3 per thread)
    if (b == 0) {
        int base2 = tid * 3;
        int v0 = (base2 + 0 < NBLK) ? g_blocksum[base2 + 0] : 0;
        int v1 = (base2 + 1 < NBLK) ? g_blocksum[base2 + 1] : 0;
        int v2 = (base2 + 2 < NBLK) ? g_blocksum[base2 + 2] : 0;
        int tsum = v0 + v1 + v2;
        int s = tsum;
#pragma unroll
        for (int d = 1; d < 32; d <<= 1) {
            int tv = __shfl_up_sync(0xffffffffu, s, d);
            if (lane >= d) s += tv;
        }
        if (lane == 31) sInts[w] = s;
        __syncthreads();
        if (tid == 0) {
            int acc = 0;
#pragma unroll
            for (int k = 0; k < 8; k++) { int t2 = sInts[k]; sInts[k] = acc; acc += t2; }
        }
        __syncthreads();
        int excl = (s - tsum) + sInts[w];
        if (base2 + 0 < NBLK) { g_blockoff[base2 + 0] = excl; excl += v0; }
        if (base2 + 1 < NBLK) { g_blockoff[base2 + 1] = excl; excl += v1; }
        if (base2 + 2 < NBLK) { g_blockoff[base2 + 2] = excl; excl += v2; }
    }
    grid_barrier();

    // phase 2c: add block offsets; init fill cursors
    {
        int off = g_blockoff[b];
        int idx = b * CHUNK + tid;
        if (tid < CHUNK && idx < N_NODES) {
            int o = g_off[idx] + off;
            g_off[idx] = o;
            g_count[idx] = o;
        }
        if (gtid == 0) g_off[N_NODES] = N_EDGES;
    }
    grid_barrier();

    // phase 3: fill CSR
    {
        const int4* src4 = (const int4*)ei;
        const int4* dst4 = (const int4*)(ei + N_EDGES);
        for (int t = gtid; t < N_EDGES / 4; t += GSTRIDE) {
            int4 sv = __ldg(&src4[t]);
            int4 d = __ldg(&dst4[t]);
            g_csr[atomicAdd(&g_count[d.x], 1)] = sv.x;
            g_csr[atomicAdd(&g_count[d.y], 1)] = sv.y;
            g_csr[atomicAdd(&g_count[d.z], 1)] = sv.z;
            g_csr[atomicAdd(&g_count[d.w], 1)] = sv.w;
        }
    }
    grid_barrier();

    // ---- layer 1: x -> g_h0 ----
    for (int tile = b; tile < NTILES; tile += NBLK)
        layer_tile<false>(x, Wl, Wr, Wout, bl, bout, g_h0, tile, tid, sFeat);
    grid_barrier();

    // ---- layer 2: g_h0 -> g_h1 ----
    for (int tile = b; tile < NTILES; tile += NBLK)
        layer_tile<false>(g_h0, Wl + 4096, Wr + 4096, Wout,
                          bl + HIDDEN, bout, g_h1, tile, tid, sFeat);
    grid_barrier();

    // ---- layer 3 + output projection: g_h1 -> out ----
    for (int tile = b; tile < NTILES; tile += NBLK)
        layer_tile<true>(g_h1, Wl + 8192, Wr + 8192, Wout,
                         bl + 2 * HIDDEN, bout, out, tile, tid, sFeat);
}

extern "C" void kernel_launch(void* const* d_in, const int* in_sizes, int n_in,
                              void* d_out, int out_size) {
    const float* x = (const float*)d_in[0];
    const int* ei = (const int*)d_in[1];
    const float* Wl = (const float*)d_in[2];
    const float* bl = (const float*)d_in[3];
    const float* Wr = (const float*)d_in[4];
    const float* Wout = (const float*)d_in[5];
    const float* bout = (const float*)d_in[6];
    float* out = (float*)d_out;

    fused_kernel<<<NBLK, TPB>>>(x, ei, Wl, bl, Wr, Wout, bout, out);
}